// round 3
// baseline (speedup 1.0000x reference)
#include <cuda_runtime.h>
#include <math.h>

// Problem constants
#define Bc   32
#define Ic   1152
#define Oc   10
#define Dc   16
#define Hc   10
#define Sc   922
#define ROW  18           // padded row stride (floats) for u in smem: 16 residues mod 32 banks, 8B-aligned
#define NTHR 320          // 10 warps: warp w handles hypothesis h = w

// Dynamic smem layout (floats unless noted):
//  u_s    : Ic*ROW           = 20736 f
//  vn     : Ic               =  1152 f
//  mu     : Hc*Dc            =   160 f
//  wpart  : Hc*Hc            =   100 f
//  loss_s : Hc               =    10 f
//  det_s  : 1 int, hmin_s : 1 int
//  sidx_s : Hc*Sc uint16     = 18440 B
// total ≈ 107,080 B -> 2 CTAs/SM (227KB limit)
#define SMEM_BYTES ((Ic*ROW + Ic + Hc*Dc + Hc*Hc + Hc + 2) * 4 + Hc*Sc*2 + 16)

extern "C" __global__ void __launch_bounds__(NTHR, 2)
ransac_routing_kernel(const float* __restrict__ u,
                      const unsigned int* __restrict__ sidx_raw,
                      float* __restrict__ out)
{
    extern __shared__ float sm[];
    float* u_s    = sm;                        // [Ic][ROW]
    float* vn     = u_s + Ic * ROW;            // [Ic]
    float* mu     = vn + Ic;                   // [Hc][Dc]
    float* wpart  = mu + Hc * Dc;              // [Hc warps][Hc]
    float* loss_s = wpart + Hc * Hc;           // [Hc]
    int*   det_s  = (int*)(loss_s + Hc);
    int*   hmin_s = det_s + 1;
    unsigned short* sidx_s = (unsigned short*)(hmin_s + 1);  // [Hc][Sc]

    const int o    = blockIdx.x;
    const int b    = blockIdx.y;
    const int tid  = threadIdx.x;
    const int w    = tid >> 5;
    const int lane = tid & 31;

    // ---- dtype detection: int64 vs int32 sample_idx -------------------------
    // For little-endian int64 indices (< 1152), every odd 32-bit word is 0.
    // For int32 data those words are top-S indices; 128 of them all-zero is impossible.
    if (w == 0) {
        unsigned a = 0;
        #pragma unroll
        for (int j = 0; j < 4; j++) a |= sidx_raw[2 * (lane * 4 + j) + 1];
        unsigned bal = __ballot_sync(0xffffffffu, a != 0);
        if (lane == 0) *det_s = (bal == 0) ? 1 : 0;
    }
    __syncthreads();
    const bool is64 = (*det_s != 0);

    // ---- Phase A1: stage u[b,:,o,:] into smem (float2 granularity) ---------
    {
        const float2* gp = (const float2*)u + ((size_t)b * Ic * Oc + o) * (Dc / 2);
        const int rstride2 = Oc * Dc / 2;   // float2 stride between i rows = 80
        for (int t = tid; t < Ic * (Dc / 2); t += NTHR) {
            int i = t >> 3, q = t & 7;
            float2 v = __ldg(gp + (size_t)i * rstride2 + q);
            *(float2*)&u_s[i * ROW + q * 2] = v;
        }
    }

    // ---- Phase A2: stage all sample indices for this (b,o) as uint16 ------
    {
        // flat element offset: ((b*Sc + s)*Oc + o)*Hc + h ; h is innermost in memory
        const size_t base = (((size_t)b * Sc) * Oc + o) * Hc;
        #pragma unroll 4
        for (int t = tid; t < Hc * Sc; t += NTHR) {
            int s = t / Hc;
            int h = t - s * Hc;
            size_t off = base + (size_t)s * (Oc * Hc) + h;
            unsigned idx = is64 ? sidx_raw[off * 2] : sidx_raw[off];
            sidx_s[h * Sc + s] = (unsigned short)idx;
        }
    }
    __syncthreads();

    // ---- Phase A3: row L2 norms --------------------------------------------
    for (int i = tid; i < Ic; i += NTHR) {
        float ss = 0.f;
        #pragma unroll
        for (int d = 0; d < Dc; d += 2) {
            float2 p = *(const float2*)&u_s[i * ROW + d];
            ss = fmaf(p.x, p.x, ss);
            ss = fmaf(p.y, p.y, ss);
        }
        vn[i] = sqrtf(ss);
    }
    __syncthreads();

    // ---- Phase B: per-hypothesis weighted mean Mu (warp w -> h = w) --------
    {
        const int h = w;   // 10 warps, Hc = 10
        float acc[Dc];
        #pragma unroll
        for (int d = 0; d < Dc; d++) acc[d] = 0.f;
        float accd = 0.f;

        const unsigned short* sp = &sidx_s[h * Sc];
        for (int s = lane; s < Sc; s += 32) {
            int idx = sp[s];
            float wv = vn[idx];
            const float* row = &u_s[idx * ROW];
            accd += wv;
            #pragma unroll
            for (int d = 0; d < Dc; d += 2) {
                float2 p = *(const float2*)&row[d];
                acc[d]     = fmaf(wv, p.x, acc[d]);
                acc[d + 1] = fmaf(wv, p.y, acc[d + 1]);
            }
        }
        // warp tree reduction (deterministic)
        #pragma unroll
        for (int off = 16; off; off >>= 1) {
            accd += __shfl_down_sync(0xffffffffu, accd, off);
            #pragma unroll
            for (int d = 0; d < Dc; d++)
                acc[d] += __shfl_down_sync(0xffffffffu, acc[d], off);
        }
        if (lane == 0) {
            float inv = 1.0f / accd;
            #pragma unroll
            for (int d = 0; d < Dc; d++) mu[h * Dc + d] = acc[d] * inv;
        }
    }
    __syncthreads();

    // ---- Phase C: losses[h] = sum_i ||u_i - Mu_h||  (all i) ----------------
    {
        float pl[Hc];
        #pragma unroll
        for (int h = 0; h < Hc; h++) pl[h] = 0.f;

        for (int i = tid; i < Ic; i += NTHR) {
            float uv[Dc];
            #pragma unroll
            for (int d = 0; d < Dc; d += 2) {
                float2 p = *(const float2*)&u_s[i * ROW + d];
                uv[d] = p.x; uv[d + 1] = p.y;
            }
            #pragma unroll
            for (int h = 0; h < Hc; h++) {
                float ss = 0.f;
                #pragma unroll
                for (int d = 0; d < Dc; d++) {
                    float t = uv[d] - mu[h * Dc + d];   // mu read is warp-broadcast
                    ss = fmaf(t, t, ss);
                }
                pl[h] += sqrtf(ss);
            }
        }
        // warp reduce each pl[h]
        #pragma unroll
        for (int off = 16; off; off >>= 1)
            #pragma unroll
            for (int h = 0; h < Hc; h++)
                pl[h] += __shfl_down_sync(0xffffffffu, pl[h], off);
        if (lane == 0) {
            #pragma unroll
            for (int h = 0; h < Hc; h++) wpart[w * Hc + h] = pl[h];
        }
    }
    __syncthreads();

    // cross-warp reduction, fixed order -> deterministic
    if (tid < Hc) {
        float s = 0.f;
        #pragma unroll
        for (int ww = 0; ww < Hc; ww++) s += wpart[ww * Hc + tid];
        loss_s[tid] = s;
    }
    __syncthreads();

    // argmin (first occurrence, like jnp.argmin)
    if (tid == 0) {
        int hm = 0; float best = loss_s[0];
        #pragma unroll
        for (int h = 1; h < Hc; h++)
            if (loss_s[h] < best) { best = loss_s[h]; hm = h; }
        *hmin_s = hm;
    }
    __syncthreads();

    // emit v[b,o,:] = Mu[:, h*]
    if (tid < Dc)
        out[((size_t)b * Oc + o) * Dc + tid] = mu[(*hmin_s) * Dc + tid];
}

extern "C" void kernel_launch(void* const* d_in, const int* in_sizes, int n_in,
                              void* d_out, int out_size)
{
    const float*        u    = (const float*)d_in[0];
    const unsigned int* sidx = (const unsigned int*)d_in[1];
    float*              out  = (float*)d_out;

    cudaFuncSetAttribute(ransac_routing_kernel,
                         cudaFuncAttributeMaxDynamicSharedMemorySize, SMEM_BYTES);

    dim3 grid(Oc, Bc);
    ransac_routing_kernel<<<grid, NTHR, SMEM_BYTES>>>(u, sidx, out);
}

// round 4
// speedup vs baseline: 1.4551x; 1.4551x over previous
#include <cuda_runtime.h>
#include <math.h>

// Problem constants
#define Bc   32
#define Ic   1152
#define Oc   10
#define Dc   16
#define Hc   10
#define Sc   922
#define HALF 461          // Sc/2, exact
#define ROW  18           // padded row stride (floats): 16 bank residues, 8B aligned
#define NTHR 640          // 20 warps
#define NW   20

// smem: u_s Ic*ROW + vn Ic + mu Hc*Dc + red NW*17 + loss Hc + 4 ints + idx u16
#define SMEM_BYTES ((Ic*ROW + Ic + Hc*Dc + NW*17 + Hc + 4) * 4 + Hc*Sc*2)

__device__ __forceinline__ float sqrt_approx(float x) {
    float r; asm("sqrt.approx.f32 %0, %1;" : "=f"(r) : "f"(x)); return r;
}
__device__ __forceinline__ float rcp_approx(float x) {
    float r; asm("rcp.approx.f32 %0, %1;" : "=f"(r) : "f"(x)); return r;
}

extern "C" __global__ void __launch_bounds__(NTHR, 2)
ransac_routing_kernel(const float* __restrict__ u,
                      const unsigned int* __restrict__ sidx_raw,
                      float* __restrict__ out)
{
    extern __shared__ float sm[];
    float* u_s    = sm;                        // [Ic][ROW]
    float* vn     = u_s + Ic * ROW;            // [Ic]
    float* mu     = vn + Ic;                   // [Hc][Dc]
    float* red    = mu + Hc * Dc;              // [NW][17] (reused [NW][Hc] in phase C)
    float* loss_s = red + NW * 17;             // [Hc]
    int*   det_s  = (int*)(loss_s + Hc);
    int*   hmin_s = det_s + 1;
    unsigned short* sidx_s = (unsigned short*)(det_s + 4);  // [Hc][Sc]

    const int o    = blockIdx.x;
    const int b    = blockIdx.y;
    const int tid  = threadIdx.x;
    const int w    = tid >> 5;
    const int lane = tid & 31;

    // ---- dtype detection: int64 vs int32 sample_idx ------------------------
    if (w == 0) {
        unsigned a = 0;
        #pragma unroll
        for (int j = 0; j < 4; j++) a |= sidx_raw[2 * (lane * 4 + j) + 1];
        unsigned bal = __ballot_sync(0xffffffffu, a != 0);
        if (lane == 0) *det_s = (bal == 0) ? 1 : 0;
    }
    __syncthreads();
    const bool is64 = (*det_s != 0);

    // ---- Phase A1: stage u[b,:,o,:] into smem (float2 granularity) ---------
    {
        const float2* gp = (const float2*)u + ((size_t)b * Ic * Oc + o) * (Dc / 2);
        const int rstride2 = Oc * Dc / 2;   // 80 float2 between i rows
        #pragma unroll 2
        for (int t = tid; t < Ic * (Dc / 2); t += NTHR) {
            int i = t >> 3, q = t & 7;
            float2 v = __ldg(gp + (size_t)i * rstride2 + q);
            *(float2*)&u_s[i * ROW + q * 2] = v;
        }
    }

    // ---- Phase A2: stage all sample indices for this (b,o) as uint16 ------
    {
        const size_t base = (((size_t)b * Sc) * Oc + o) * Hc;
        #pragma unroll 2
        for (int t = tid; t < Hc * Sc; t += NTHR) {
            int s = t / Hc;
            int h = t - s * Hc;
            size_t off = base + (size_t)s * (Oc * Hc) + h;
            unsigned idx = is64 ? sidx_raw[off * 2] : sidx_raw[off];
            sidx_s[h * Sc + s] = (unsigned short)idx;
        }
    }
    __syncthreads();

    // ---- Phase A3: row L2 norms --------------------------------------------
    #pragma unroll
    for (int k = 0; k < 2; k++) {
        int i = tid + k * NTHR;
        if (i < Ic) {
            float ss = 0.f;
            #pragma unroll
            for (int d = 0; d < Dc; d += 2) {
                float2 p = *(const float2*)&u_s[i * ROW + d];
                ss = fmaf(p.x, p.x, ss);
                ss = fmaf(p.y, p.y, ss);
            }
            vn[i] = sqrt_approx(ss);
        }
    }
    __syncthreads();

    // ---- Phase B: weighted mean; warp w -> (h = w/2, half = w&1) -----------
    {
        const int h    = w >> 1;
        const int part = w & 1;
        const unsigned short* sp = &sidx_s[h * Sc + part * HALF];

        float acc[Dc];
        #pragma unroll
        for (int d = 0; d < Dc; d++) acc[d] = 0.f;
        float accd = 0.f;

        #pragma unroll 3
        for (int k = 0; k < 15; k++) {
            int s = lane + k * 32;
            if (s < HALF) {
                int idx = sp[s];
                float wv = vn[idx];
                const float* row = &u_s[idx * ROW];
                accd += wv;
                #pragma unroll
                for (int d = 0; d < Dc; d += 2) {
                    float2 p = *(const float2*)&row[d];
                    acc[d]     = fmaf(wv, p.x, acc[d]);
                    acc[d + 1] = fmaf(wv, p.y, acc[d + 1]);
                }
            }
        }
        // warp tree reduction (deterministic)
        #pragma unroll
        for (int off = 16; off; off >>= 1) {
            accd += __shfl_down_sync(0xffffffffu, accd, off);
            #pragma unroll
            for (int d = 0; d < Dc; d++)
                acc[d] += __shfl_down_sync(0xffffffffu, acc[d], off);
        }
        if (lane == 0) {
            #pragma unroll
            for (int d = 0; d < Dc; d++) red[w * 17 + d] = acc[d];
            red[w * 17 + Dc] = accd;
        }
    }
    __syncthreads();

    // combine the two halves per h -> mu (fixed order, deterministic)
    if (tid < Hc * Dc) {
        int h = tid >> 4, d = tid & 15;
        float num = red[(2 * h) * 17 + d]  + red[(2 * h + 1) * 17 + d];
        float den = red[(2 * h) * 17 + Dc] + red[(2 * h + 1) * 17 + Dc];
        mu[h * Dc + d] = num * rcp_approx(den);
    }
    __syncthreads();

    // ---- Phase C: losses[h] = sum_i ||u_i - Mu_h||  (all i) ----------------
    {
        float pl[Hc];
        #pragma unroll
        for (int h = 0; h < Hc; h++) pl[h] = 0.f;

        #pragma unroll
        for (int k = 0; k < 2; k++) {
            int i = tid + k * NTHR;
            if (i < Ic) {
                float uv[Dc];
                #pragma unroll
                for (int d = 0; d < Dc; d += 2) {
                    float2 p = *(const float2*)&u_s[i * ROW + d];
                    uv[d] = p.x; uv[d + 1] = p.y;
                }
                #pragma unroll
                for (int h = 0; h < Hc; h++) {
                    float ss = 0.f;
                    #pragma unroll
                    for (int d = 0; d < Dc; d++) {
                        float t = uv[d] - mu[h * Dc + d];   // broadcast LDS
                        ss = fmaf(t, t, ss);
                    }
                    pl[h] += sqrt_approx(ss);
                }
            }
        }
        #pragma unroll
        for (int off = 16; off; off >>= 1)
            #pragma unroll
            for (int h = 0; h < Hc; h++)
                pl[h] += __shfl_down_sync(0xffffffffu, pl[h], off);
        if (lane == 0) {
            #pragma unroll
            for (int h = 0; h < Hc; h++) red[w * 17 + h] = pl[h];
        }
    }
    __syncthreads();

    // cross-warp reduction, fixed order -> deterministic
    if (tid < Hc) {
        float s = 0.f;
        #pragma unroll
        for (int ww = 0; ww < NW; ww++) s += red[ww * 17 + tid];
        loss_s[tid] = s;
    }
    __syncthreads();

    // argmin (first occurrence, like jnp.argmin)
    if (tid == 0) {
        int hm = 0; float best = loss_s[0];
        #pragma unroll
        for (int h = 1; h < Hc; h++)
            if (loss_s[h] < best) { best = loss_s[h]; hm = h; }
        *hmin_s = hm;
    }
    __syncthreads();

    // emit v[b,o,:] = Mu[:, h*]
    if (tid < Dc)
        out[((size_t)b * Oc + o) * Dc + tid] = mu[(*hmin_s) * Dc + tid];
}

extern "C" void kernel_launch(void* const* d_in, const int* in_sizes, int n_in,
                              void* d_out, int out_size)
{
    const float*        u    = (const float*)d_in[0];
    const unsigned int* sidx = (const unsigned int*)d_in[1];
    float*              out  = (float*)d_out;

    cudaFuncSetAttribute(ransac_routing_kernel,
                         cudaFuncAttributeMaxDynamicSharedMemorySize, SMEM_BYTES);

    dim3 grid(Oc, Bc);
    ransac_routing_kernel<<<grid, NTHR, SMEM_BYTES>>>(u, sidx, out);
}

// round 5
// speedup vs baseline: 1.6070x; 1.1044x over previous
#include <cuda_runtime.h>

// Problem constants
#define Bc    32
#define Ic    1152
#define Oc    10
#define Dc    16
#define Hc    10
#define Sc    922
#define ROW   20        // floats per padded row (80B, 16B-aligned for float4)
#define NTHR  640       // 20 warps
#define NW    20
#define HALF_I 576      // Ic/2
#define CLCAP  232      // complement-list capacity per (h,half); total complement per h = 230

// smem layout (see pointers in kernel):
// u_s Ic*ROW f (92160B) | mu 160 f | red NW*17 f | loss Hc f | 2 ints |
// mark Ic*Hc bytes (11520B; reused as red2 after compaction) | clist Hc*2*CLCAP u16 (9280B)
#define SMEM_BYTES ((Ic*ROW + Hc*Dc + NW*17 + Hc + 2) * 4 + Ic*Hc + Hc*2*CLCAP*2)

__device__ __forceinline__ float sqrt_approx(float x) {
    float r; asm("sqrt.approx.f32 %0, %1;" : "=f"(r) : "f"(x)); return r;
}

// Load one padded row into 16 regs and return sum of squares.
// MUST be the single shared implementation so vn recomputation is bit-identical
// between the T-pass and the complement gather.
__device__ __forceinline__ float load_row(const float* __restrict__ rp, float f[16]) {
    float4 a = *(const float4*)(rp + 0);
    float4 b = *(const float4*)(rp + 4);
    float4 c = *(const float4*)(rp + 8);
    float4 d = *(const float4*)(rp + 12);
    f[0]=a.x; f[1]=a.y; f[2]=a.z; f[3]=a.w;
    f[4]=b.x; f[5]=b.y; f[6]=b.z; f[7]=b.w;
    f[8]=c.x; f[9]=c.y; f[10]=c.z; f[11]=c.w;
    f[12]=d.x; f[13]=d.y; f[14]=d.z; f[15]=d.w;
    float ss = 0.f;
    #pragma unroll
    for (int k = 0; k < 16; k++) ss = fmaf(f[k], f[k], ss);
    return ss;
}

extern "C" __global__ void __launch_bounds__(NTHR, 2)
ransac_routing_kernel(const float* __restrict__ u,
                      const unsigned int* __restrict__ sidx_raw,
                      float* __restrict__ out)
{
    extern __shared__ float sm[];
    float* u_s    = sm;                         // [Ic][ROW]
    float* mu     = u_s + Ic * ROW;             // [Hc][Dc]
    float* red    = mu + Hc * Dc;               // [NW][17]  (T partials; reused for loss)
    float* loss_s = red + NW * 17;              // [Hc]
    int*   det_s  = (int*)(loss_s + Hc);
    int*   hmin_s = det_s + 1;
    unsigned char*  mark  = (unsigned char*)(det_s + 2);       // [Hc][Ic] bytes
    float*          red2  = (float*)mark;                      // [NW][17] after mark dies
    unsigned short* clist = (unsigned short*)(mark + Ic * Hc); // [Hc][2][CLCAP]

    const int o    = blockIdx.x;
    const int b    = blockIdx.y;
    const int tid  = threadIdx.x;
    const int w    = tid >> 5;
    const int lane = tid & 31;

    // ---- zero mark bytes (2880 words) --------------------------------------
    {
        unsigned int* mw = (unsigned int*)mark;
        #pragma unroll
        for (int k = 0; k < 5; k++) {
            int t = tid + k * NTHR;
            if (t < (Ic * Hc) / 4) mw[t] = 0;
        }
    }
    // ---- dtype detect: int64 vs int32 (high words all-zero <=> int64) -----
    if (w == 0) {
        unsigned a = 0;
        #pragma unroll
        for (int j = 0; j < 4; j++) a |= sidx_raw[2 * (lane * 4 + j) + 1];
        unsigned bal = __ballot_sync(0xffffffffu, a != 0);
        if (lane == 0) *det_s = (bal == 0) ? 1 : 0;
    }
    __syncthreads();
    const bool is64 = (*det_s != 0);

    // ---- Phase A1: stage u[b,:,o,:] via float4 (conflict-free STS.128) ----
    {
        const float4* gp = (const float4*)u + ((size_t)b * Ic * Oc + o) * (Dc / 4);
        const int rs4 = Oc * Dc / 4;  // 40 float4 between i rows
        #pragma unroll
        for (int k = 0; k < 8; k++) {
            int t = tid + k * NTHR;
            if (t < Ic * 4) {
                int i = t >> 2, q = t & 3;
                float4 v = __ldg(gp + (size_t)i * rs4 + q);
                *(float4*)&u_s[i * ROW + q * 4] = v;
            }
        }
    }
    // ---- Phase A2: load indices, scatter mark bytes (no idx staging) ------
    {
        const size_t base = (((size_t)b * Sc) * Oc + o) * Hc;
        if (is64) {
            const uint2* p64 = (const uint2*)sidx_raw;  // full-sector uint2 loads
            #pragma unroll
            for (int k = 0; k < 15; k++) {
                int t = tid + k * NTHR;
                if (t < Sc * Hc) {
                    int s = t / Hc;
                    int h = t - s * Hc;
                    uint2 v = __ldg(p64 + base + (size_t)s * (Oc * Hc) + h);
                    mark[h * Ic + v.x] = 1;   // indices distinct per h -> no conflict
                }
            }
        } else {
            #pragma unroll
            for (int k = 0; k < 15; k++) {
                int t = tid + k * NTHR;
                if (t < Sc * Hc) {
                    int s = t / Hc;
                    int h = t - s * Hc;
                    unsigned v = __ldg(sidx_raw + base + (size_t)s * (Oc * Hc) + h);
                    mark[h * Ic + v] = 1;
                }
            }
        }
    }
    __syncthreads();

    const int h    = w >> 1;     // warp -> (hypothesis, half)
    const int part = w & 1;

    // ---- Phase B1: global sums T[d], N over all rows + complement compaction
    {
        float tAcc[Dc];
        #pragma unroll
        for (int d = 0; d < Dc; d++) tAcc[d] = 0.f;
        float nAcc = 0.f;

        #pragma unroll
        for (int k = 0; k < 2; k++) {
            int i = tid + k * NTHR;
            if (i < Ic) {
                float f[16];
                float ss = load_row(&u_s[i * ROW], f);
                float wv = sqrt_approx(ss);
                nAcc += wv;
                #pragma unroll
                for (int d = 0; d < Dc; d++) tAcc[d] = fmaf(wv, f[d], tAcc[d]);
            }
        }
        #pragma unroll
        for (int off = 16; off; off >>= 1) {
            nAcc += __shfl_down_sync(0xffffffffu, nAcc, off);
            #pragma unroll
            for (int d = 0; d < Dc; d++)
                tAcc[d] += __shfl_down_sync(0xffffffffu, tAcc[d], off);
        }
        if (lane == 0) {
            #pragma unroll
            for (int d = 0; d < Dc; d++) red[w * 17 + d] = tAcc[d];
            red[w * 17 + 16] = nAcc;
        }
    }
    // compaction: complement indices of half [part] for hypothesis h
    int cnt = 0;
    {
        const unsigned char* mh = &mark[h * Ic + part * HALF_I];
        unsigned short* mylist = &clist[(h * 2 + part) * CLCAP];
        #pragma unroll
        for (int j = 0; j < HALF_I / 32; j++) {
            int i = j * 32 + lane;
            int m = mh[i];
            unsigned bal = __ballot_sync(0xffffffffu, m == 0);
            int pre = __popc(bal & ((1u << lane) - 1u));
            if (m == 0) mylist[cnt + pre] = (unsigned short)(part * HALF_I + i);
            cnt += __popc(bal);
        }
    }
    __syncthreads();   // mark now dead everywhere -> red2 may alias it

    // ---- Phase B2: gather only the ~230-row complement -> C_h partials ----
    {
        float cAcc[Dc];
        #pragma unroll
        for (int d = 0; d < Dc; d++) cAcc[d] = 0.f;
        float cdAcc = 0.f;

        const unsigned short* mylist = &clist[(h * 2 + part) * CLCAP];
        for (int s = lane; s < cnt; s += 32) {
            int i = mylist[s];
            float f[16];
            float ss = load_row(&u_s[i * ROW], f);
            float wv = sqrt_approx(ss);
            cdAcc += wv;
            #pragma unroll
            for (int d = 0; d < Dc; d++) cAcc[d] = fmaf(wv, f[d], cAcc[d]);
        }
        #pragma unroll
        for (int off = 16; off; off >>= 1) {
            cdAcc += __shfl_down_sync(0xffffffffu, cdAcc, off);
            #pragma unroll
            for (int d = 0; d < Dc; d++)
                cAcc[d] += __shfl_down_sync(0xffffffffu, cAcc[d], off);
        }
        if (lane == 0) {
            #pragma unroll
            for (int d = 0; d < Dc; d++) red2[w * 17 + d] = cAcc[d];
            red2[w * 17 + 16] = cdAcc;
        }
    }
    __syncthreads();

    // ---- mu[h] = (T - C_h) / (N - c_h)  (fixed order, deterministic) ------
    if (tid < Hc * Dc) {
        int hh = tid >> 4, d = tid & 15;
        float T = 0.f, N = 0.f;
        #pragma unroll
        for (int ww = 0; ww < NW; ww++) { T += red[ww * 17 + d]; N += red[ww * 17 + 16]; }
        float C = red2[(2 * hh) * 17 + d]  + red2[(2 * hh + 1) * 17 + d];
        float c = red2[(2 * hh) * 17 + 16] + red2[(2 * hh + 1) * 17 + 16];
        mu[hh * Dc + d] = (T - C) / (N - c);
    }
    __syncthreads();

    // ---- Phase C: losses[h] = sum_i ||u_i - mu_h|| ------------------------
    {
        float pl[Hc];
        #pragma unroll
        for (int hh = 0; hh < Hc; hh++) pl[hh] = 0.f;

        #pragma unroll
        for (int k = 0; k < 2; k++) {
            int i = tid + k * NTHR;
            if (i < Ic) {
                float f[16];
                load_row(&u_s[i * ROW], f);
                #pragma unroll
                for (int hh = 0; hh < Hc; hh++) {
                    const float4* mp = (const float4*)&mu[hh * Dc];  // broadcast LDS.128
                    float4 m0 = mp[0], m1 = mp[1], m2 = mp[2], m3 = mp[3];
                    float mv[16] = {m0.x,m0.y,m0.z,m0.w, m1.x,m1.y,m1.z,m1.w,
                                    m2.x,m2.y,m2.z,m2.w, m3.x,m3.y,m3.z,m3.w};
                    float ss = 0.f;
                    #pragma unroll
                    for (int d = 0; d < Dc; d++) {
                        float t = f[d] - mv[d];
                        ss = fmaf(t, t, ss);
                    }
                    pl[hh] += sqrt_approx(ss);
                }
            }
        }
        #pragma unroll
        for (int off = 16; off; off >>= 1)
            #pragma unroll
            for (int hh = 0; hh < Hc; hh++)
                pl[hh] += __shfl_down_sync(0xffffffffu, pl[hh], off);
        if (lane == 0) {
            #pragma unroll
            for (int hh = 0; hh < Hc; hh++) red[w * 17 + hh] = pl[hh];
        }
    }
    __syncthreads();

    // ---- final: loss combine, argmin (first occurrence), emit -------------
    if (w == 0) {
        if (lane < Hc) {
            float s = 0.f;
            #pragma unroll
            for (int ww = 0; ww < NW; ww++) s += red[ww * 17 + lane];
            loss_s[lane] = s;
        }
        __syncwarp();
        if (lane == 0) {
            int hm = 0; float best = loss_s[0];
            #pragma unroll
            for (int hh = 1; hh < Hc; hh++)
                if (loss_s[hh] < best) { best = loss_s[hh]; hm = hh; }
            *hmin_s = hm;
        }
        __syncwarp();
        if (lane < Dc)
            out[((size_t)b * Oc + o) * Dc + lane] = mu[(*hmin_s) * Dc + lane];
    }
}

extern "C" void kernel_launch(void* const* d_in, const int* in_sizes, int n_in,
                              void* d_out, int out_size)
{
    const float*        u    = (const float*)d_in[0];
    const unsigned int* sidx = (const unsigned int*)d_in[1];
    float*              out  = (float*)d_out;

    cudaFuncSetAttribute(ransac_routing_kernel,
                         cudaFuncAttributeMaxDynamicSharedMemorySize, SMEM_BYTES);

    dim3 grid(Oc, Bc);
    ransac_routing_kernel<<<grid, NTHR, SMEM_BYTES>>>(u, sidx, out);
}

// round 6
// speedup vs baseline: 2.5332x; 1.5763x over previous
#include <cuda_runtime.h>

// Problem constants
#define Bc     32
#define Ic     1152
#define Oc     10
#define Dc     16
#define Hc     10
#define Sc     922
#define HALF_I 576
#define ROW    20          // padded row stride (floats), 16B-aligned
#define NPAIR  (Bc * Oc)   // 320
#define K1_THR 256
#define K2_THR 256

// Inter-kernel scratch: [pair][half][slot][17]
// slot 0      : T[0..15], N at [16]        (sums over this half's rows)
// slot 1 + h  : C_h[0..15], c_h at [16]    (sums over this half's COMPLEMENT rows of h)
__device__ float g_part[NPAIR][2][11][17];

// K1 dynamic smem: u_s 576*20 f | vnS 576 f | red 8*17 f | bm 180 u32 | det 1
#define K1_SMEM ((HALF_I*ROW + HALF_I + 8*17 + 181) * 4)

__device__ __forceinline__ float sqrt_approx(float x) {
    float r; asm("sqrt.approx.f32 %0, %1;" : "=f"(r) : "f"(x)); return r;
}

__device__ __forceinline__ void load_row(const float* __restrict__ rp, float f[16]) {
    float4 a = *(const float4*)(rp + 0);
    float4 b = *(const float4*)(rp + 4);
    float4 c = *(const float4*)(rp + 8);
    float4 d = *(const float4*)(rp + 12);
    f[0]=a.x; f[1]=a.y; f[2]=a.z;  f[3]=a.w;
    f[4]=b.x; f[5]=b.y; f[6]=b.z;  f[7]=b.w;
    f[8]=c.x; f[9]=c.y; f[10]=c.z; f[11]=c.w;
    f[12]=d.x; f[13]=d.y; f[14]=d.z; f[15]=d.w;
}

// ============================ K1: partial sums ==============================
extern "C" __global__ void __launch_bounds__(K1_THR, 4)
k1_partials(const float* __restrict__ u, const unsigned int* __restrict__ sidx_raw)
{
    extern __shared__ float sm[];
    float*    u_s = sm;                       // [HALF_I][ROW]
    float*    vnS = u_s + HALF_I * ROW;       // [HALF_I]
    float*    red = vnS + HALF_I;             // [8][17]
    unsigned* bm  = (unsigned*)(red + 8*17);  // [Hc][18] bitmap of SAMPLED rows (this half)
    int*      det = (int*)(bm + Hc * 18);

    const int o    = blockIdx.x;
    const int b    = blockIdx.y;
    const int half = blockIdx.z;
    const int pair = b * Oc + o;
    const int i0   = half * HALF_I;
    const int tid  = threadIdx.x;
    const int w    = tid >> 5;
    const int lane = tid & 31;

    if (tid < Hc * 18) bm[tid] = 0u;
    // dtype detect: int64 (odd 32-bit words of first 128 elems all zero) vs int32
    if (w == 0) {
        unsigned a = 0;
        #pragma unroll
        for (int j = 0; j < 4; j++) a |= sidx_raw[2 * (lane * 4 + j) + 1];
        unsigned bal = __ballot_sync(0xffffffffu, a != 0);
        if (lane == 0) *det = (bal == 0) ? 1 : 0;
    }
    __syncthreads();
    const bool is64 = (*det != 0);

    // ---- stage this half's u rows into smem (coalesced float4) -------------
    {
        const float4* gp = (const float4*)u + ((size_t)((size_t)b * Ic + i0) * Oc + o) * 4;
        #pragma unroll
        for (int k = 0; k < 9; k++) {
            int t = tid + k * K1_THR;
            if (t < HALF_I * 4) {
                int i = t >> 2, q = t & 3;
                float4 v = __ldg(gp + (size_t)i * (Oc * 4) + q);
                *(float4*)&u_s[i * ROW + q * 4] = v;
            }
        }
    }
    // ---- stream sidx slice, mark sampled rows of THIS half in bitmap -------
    {
        const size_t sbase = (((size_t)b * Sc) * Oc + o) * Hc;
        #pragma unroll 4
        for (int k = 0; k < 37; k++) {
            int t = tid + k * K1_THR;
            if (t < Sc * Hc) {
                int s = (int)(((unsigned)t * 52429u) >> 19);   // t/10 for t<81920
                int h = t - s * 10;
                size_t off = sbase + (size_t)s * (Oc * Hc) + h;
                unsigned v = is64 ? __ldg(sidx_raw + off * 2) : __ldg(sidx_raw + off);
                unsigned loc = v - (unsigned)i0;
                if (loc < HALF_I)
                    atomicOr(&bm[h * 18 + (loc >> 5)], 1u << (loc & 31));
            }
        }
    }
    __syncthreads();

    // ---- norms + T/N partials over this half -------------------------------
    {
        float tA[17];
        #pragma unroll
        for (int j = 0; j < 17; j++) tA[j] = 0.f;

        #pragma unroll
        for (int k = 0; k < 3; k++) {
            int i = tid + k * K1_THR;
            if (i < HALF_I) {
                float f[16];
                load_row(&u_s[i * ROW], f);
                float ss = 0.f;
                #pragma unroll
                for (int d = 0; d < Dc; d++) ss = fmaf(f[d], f[d], ss);
                float vn = sqrt_approx(ss);
                vnS[i] = vn;
                tA[16] += vn;
                #pragma unroll
                for (int d = 0; d < Dc; d++) tA[d] = fmaf(vn, f[d], tA[d]);
            }
        }
        #pragma unroll
        for (int off = 16; off; off >>= 1)
            #pragma unroll
            for (int j = 0; j < 17; j++)
                tA[j] += __shfl_down_sync(0xffffffffu, tA[j], off);
        if (lane == 0) {
            #pragma unroll
            for (int j = 0; j < 17; j++) red[w * 17 + j] = tA[j];
        }
    }
    __syncthreads();

    // write T/N partial (fixed-order cross-warp sum)
    if (tid < 17) {
        float s = 0.f;
        #pragma unroll
        for (int ww = 0; ww < 8; ww++) s += red[ww * 17 + tid];
        g_part[pair][half][0][tid] = s;
    }

    // ---- complement gather: warp w -> h = w (and w<2 -> h = w+8) -----------
    #pragma unroll
    for (int rep = 0; rep < 2; rep++) {
        int hh = w + rep * 8;
        if (hh < Hc) {
            float cA[17];
            #pragma unroll
            for (int j = 0; j < 17; j++) cA[j] = 0.f;

            #pragma unroll 3
            for (int wd = 0; wd < 18; wd++) {
                unsigned bits = bm[hh * 18 + wd];        // broadcast LDS
                if (!((bits >> lane) & 1u)) {            // complement bit
                    int i = wd * 32 + lane;
                    float f[16];
                    load_row(&u_s[i * ROW], f);
                    float vn = vnS[i];                   // identical value to T-pass
                    cA[16] += vn;
                    #pragma unroll
                    for (int d = 0; d < Dc; d++) cA[d] = fmaf(vn, f[d], cA[d]);
                }
            }
            #pragma unroll
            for (int off = 16; off; off >>= 1)
                #pragma unroll
                for (int j = 0; j < 17; j++)
                    cA[j] += __shfl_down_sync(0xffffffffu, cA[j], off);
            if (lane == 0) {
                #pragma unroll
                for (int j = 0; j < 17; j++) g_part[pair][half][1 + hh][j] = cA[j];
            }
        }
    }
}

// ==================== K2: Mu, losses, argmin, emit ==========================
extern "C" __global__ void __launch_bounds__(K2_THR, 4)
k2_loss(const float* __restrict__ u, float* __restrict__ out)
{
    __shared__ float u_c[128 * ROW];   // one 128-row chunk
    __shared__ float mu[Hc * Dc];
    __shared__ float mm[Hc];           // ||mu_h||^2
    __shared__ float red[8 * 5];
    __shared__ float loss_s[Hc];
    __shared__ int   hmin;

    const int o    = blockIdx.x;
    const int b    = blockIdx.y;
    const int pair = b * Oc + o;
    const int tid  = threadIdx.x;
    const int w    = tid >> 5;
    const int lane = tid & 31;
    const int r    = tid & 127;        // row slot within chunk
    const int g    = tid >> 7;         // hypothesis group: g=0 -> h 0..4, g=1 -> h 5..9

    // ---- Mu[h][d] = (T - C_h) / (N - c_h) ---------------------------------
    if (tid < Hc * Dc) {
        int h = tid >> 4, d = tid & 15;
        float T = g_part[pair][0][0][d]      + g_part[pair][1][0][d];
        float N = g_part[pair][0][0][16]     + g_part[pair][1][0][16];
        float C = g_part[pair][0][1 + h][d]  + g_part[pair][1][1 + h][d];
        float c = g_part[pair][0][1 + h][16] + g_part[pair][1][1 + h][16];
        mu[tid] = (T - C) / (N - c);
    }
    __syncthreads();
    if (tid < Hc) {
        float s = 0.f;
        #pragma unroll
        for (int d = 0; d < Dc; d++) s = fmaf(mu[tid * 16 + d], mu[tid * 16 + d], s);
        mm[tid] = s;
    }

    // ---- chunked loss pass: losses[h] = sum_i sqrt(||u||^2 - 2 u.mu + ||mu||^2)
    float pl[5] = {0.f, 0.f, 0.f, 0.f, 0.f};
    const float4* gp = (const float4*)u + ((size_t)((size_t)b * Ic) * Oc + o) * 4;

    for (int ch = 0; ch < 9; ch++) {
        __syncthreads();   // prev-chunk reads done; also covers mm on ch=0
        #pragma unroll
        for (int k = 0; k < 2; k++) {
            int t = tid + k * K2_THR;
            int i = t >> 2, q = t & 3;
            float4 v = __ldg(gp + (size_t)(ch * 128 + i) * (Oc * 4) + q);
            *(float4*)&u_c[i * ROW + q * 4] = v;
        }
        __syncthreads();

        float f[16];
        load_row(&u_c[r * ROW], f);
        float ss = 0.f;
        #pragma unroll
        for (int d = 0; d < Dc; d++) ss = fmaf(f[d], f[d], ss);

        #pragma unroll
        for (int j = 0; j < 5; j++) {
            int h = g * 5 + j;
            const float4* mp = (const float4*)&mu[h * 16];   // broadcast LDS.128
            float4 m0 = mp[0], m1 = mp[1], m2 = mp[2], m3 = mp[3];
            float dot = 0.f;
            dot = fmaf(f[0],  m0.x, dot); dot = fmaf(f[1],  m0.y, dot);
            dot = fmaf(f[2],  m0.z, dot); dot = fmaf(f[3],  m0.w, dot);
            dot = fmaf(f[4],  m1.x, dot); dot = fmaf(f[5],  m1.y, dot);
            dot = fmaf(f[6],  m1.z, dot); dot = fmaf(f[7],  m1.w, dot);
            dot = fmaf(f[8],  m2.x, dot); dot = fmaf(f[9],  m2.y, dot);
            dot = fmaf(f[10], m2.z, dot); dot = fmaf(f[11], m2.w, dot);
            dot = fmaf(f[12], m3.x, dot); dot = fmaf(f[13], m3.y, dot);
            dot = fmaf(f[14], m3.z, dot); dot = fmaf(f[15], m3.w, dot);
            float val = fmaf(-2.f, dot, ss + mm[h]);
            pl[j] += sqrt_approx(fmaxf(val, 0.f));
        }
    }
    // warp reduce (warps 0-3 are g=0, warps 4-7 are g=1)
    #pragma unroll
    for (int off = 16; off; off >>= 1)
        #pragma unroll
        for (int j = 0; j < 5; j++)
            pl[j] += __shfl_down_sync(0xffffffffu, pl[j], off);
    if (lane == 0) {
        #pragma unroll
        for (int j = 0; j < 5; j++) red[w * 5 + j] = pl[j];
    }
    __syncthreads();

    // combine to losses[h] (fixed order), argmin (first occurrence), emit
    if (tid < Hc) {
        int g2 = tid / 5, j = tid - g2 * 5;
        float s = 0.f;
        #pragma unroll
        for (int ww = 0; ww < 4; ww++) s += red[(g2 * 4 + ww) * 5 + j];
        loss_s[tid] = s;
    }
    __syncthreads();
    if (tid == 0) {
        int hm = 0; float best = loss_s[0];
        #pragma unroll
        for (int h = 1; h < Hc; h++)
            if (loss_s[h] < best) { best = loss_s[h]; hm = h; }
        hmin = hm;
    }
    __syncthreads();
    if (tid < Dc)
        out[(size_t)pair * Dc + tid] = mu[hmin * Dc + tid];
}

extern "C" void kernel_launch(void* const* d_in, const int* in_sizes, int n_in,
                              void* d_out, int out_size)
{
    const float*        u    = (const float*)d_in[0];
    const unsigned int* sidx = (const unsigned int*)d_in[1];
    float*              out  = (float*)d_out;

    cudaFuncSetAttribute(k1_partials,
                         cudaFuncAttributeMaxDynamicSharedMemorySize, K1_SMEM);

    k1_partials<<<dim3(Oc, Bc, 2), K1_THR, K1_SMEM>>>(u, sidx);
    k2_loss<<<dim3(Oc, Bc), K2_THR>>>(u, out);
}